// round 15
// baseline (speedup 1.0000x reference)
#include <cuda_runtime.h>
#include <cuda_fp16.h>

#define N_NODES    200000
#define N_EDGES    3200000
#define N_GRAPHS   4000
#define SCAN_ELEMS 2048
#define SCAN_NBLK  ((N_NODES + SCAN_ELEMS - 1) / SCAN_ELEMS)   // 98

// ---------------- device scratch (no runtime allocation) --------------------
__device__ int    g_count[N_NODES];
__device__ int    g_rowptr[N_NODES + 1];
__device__ int    g_bsums[SCAN_NBLK];
__device__ int    g_rank[N_EDGES];
__device__ int    g_srclist[N_EDGES];
__device__ __half g_x16[N_NODES * 32];    // fp16 copy of x (for gathers)
__device__ __half g_h1[N_NODES * 64];     // relu(conv1), fp16
__device__ float  g_pool[N_GRAPHS * 64];

// ---------------------------------------------------------------------------
// Prep: zero counters/pool and convert x -> fp16
// ---------------------------------------------------------------------------
__global__ __launch_bounds__(256) void k_prep(const float* __restrict__ x) {
    int i = blockIdx.x * blockDim.x + threadIdx.x;
    int stride = gridDim.x * blockDim.x;
    for (int t = i; t < N_NODES * 16; t += stride) {       // 3.2M float2
        float2 v = __ldg((const float2*)x + t);
        ((__half2*)g_x16)[t] = __floats2half2_rn(v.x, v.y);
    }
    for (int t = i; t < N_NODES; t += stride) g_count[t] = 0;
    for (int t = i; t < N_GRAPHS * 64; t += stride) g_pool[t] = 0.f;
}

// ---------------------------------------------------------------------------
// CSR build: histogram of dst; atomic return value IS the within-bucket rank.
// ---------------------------------------------------------------------------
__global__ __launch_bounds__(256) void k_hist(const int* __restrict__ ei) {
    int t = blockIdx.x * blockDim.x + threadIdx.x;
    int e = t * 4;
    if (e >= N_EDGES) return;
    int4 d4 = __ldg((const int4*)(ei + N_EDGES) + t);
    g_rank[e + 0] = atomicAdd(&g_count[d4.x], 1);
    g_rank[e + 1] = atomicAdd(&g_count[d4.y], 1);
    g_rank[e + 2] = atomicAdd(&g_count[d4.z], 1);
    g_rank[e + 3] = atomicAdd(&g_count[d4.w], 1);
}

// Scan pass 1: per-block exclusive scan of counts (2048 elems / block of 512)
__global__ __launch_bounds__(512) void k_scan1() {
    __shared__ int warp_sums[16];
    int t = threadIdx.x;
    int base = blockIdx.x * SCAN_ELEMS + t * 4;
    int c0 = (base + 0 < N_NODES) ? g_count[base + 0] : 0;
    int c1 = (base + 1 < N_NODES) ? g_count[base + 1] : 0;
    int c2 = (base + 2 < N_NODES) ? g_count[base + 2] : 0;
    int c3 = (base + 3 < N_NODES) ? g_count[base + 3] : 0;
    int s = c0 + c1 + c2 + c3;
    int lane = t & 31, wid = t >> 5;
    int v = s;
    #pragma unroll
    for (int o = 1; o < 32; o <<= 1) {
        int u = __shfl_up_sync(0xFFFFFFFFu, v, o);
        if (lane >= o) v += u;
    }
    if (lane == 31) warp_sums[wid] = v;
    __syncthreads();
    if (wid == 0) {
        int w = (lane < 16) ? warp_sums[lane] : 0;
        #pragma unroll
        for (int o = 1; o < 16; o <<= 1) {
            int u = __shfl_up_sync(0xFFFFFFFFu, w, o);
            if (lane >= o) w += u;
        }
        if (lane < 16) warp_sums[lane] = w;
    }
    __syncthreads();
    int excl = v - s + (wid > 0 ? warp_sums[wid - 1] : 0);
    if (base + 0 < N_NODES) g_rowptr[base + 0] = excl;
    if (base + 1 < N_NODES) g_rowptr[base + 1] = excl + c0;
    if (base + 2 < N_NODES) g_rowptr[base + 2] = excl + c0 + c1;
    if (base + 3 < N_NODES) g_rowptr[base + 3] = excl + c0 + c1 + c2;
    if (t == 511) g_bsums[blockIdx.x] = warp_sums[15];
}

// Scan pass 2: exclusive scan of 98 block sums (single block)
__global__ __launch_bounds__(128) void k_scan2() {
    __shared__ int sh[128];
    int t = threadIdx.x;
    sh[t] = (t < SCAN_NBLK) ? g_bsums[t] : 0;
    __syncthreads();
    int v = sh[t];
    #pragma unroll
    for (int o = 1; o < 128; o <<= 1) {
        int u = (t >= o) ? sh[t - o] : 0;
        __syncthreads();
        v += u;
        sh[t] = v;
        __syncthreads();
    }
    if (t < SCAN_NBLK) g_bsums[t] = (t > 0) ? sh[t - 1] : 0;
}

// Scan pass 3: add block offsets
__global__ __launch_bounds__(256) void k_scan3() {
    int i = blockIdx.x * blockDim.x + threadIdx.x;
    if (i == 0) g_rowptr[N_NODES] = N_EDGES;
    if (i >= N_NODES) return;
    g_rowptr[i] += g_bsums[i / SCAN_ELEMS];
}

// CSR fill, atomic-free: pos = rowptr[dst] + rank[e]
__global__ __launch_bounds__(256) void k_fill(const int* __restrict__ ei) {
    int e = blockIdx.x * blockDim.x + threadIdx.x;
    if (e >= N_EDGES) return;
    int s = __ldg(ei + e);
    int d = __ldg(ei + N_EDGES + e);
    int pos = __ldg(g_rowptr + d) + __ldg(g_rank + e);
    g_srclist[pos] = s;
}

// ---------------------------------------------------------------------------
// Fused conv1: 8 warps each gather-mean 4 nodes (32-dim, lane=dim) from fp16 x,
// single predicated 16-wide loop (uniform MLP-16, no scalar tail), then
// register-blocked transform: h1 = relu(mean @ W1_l.T + b1 + x @ W1_r.T)
// ---------------------------------------------------------------------------
__global__ __launch_bounds__(256) void k_conv1(const float* __restrict__ x,
                                               const float* __restrict__ W_l,
                                               const float* __restrict__ b,
                                               const float* __restrict__ W_r) {
    __shared__ float sWlT[32 * 65];   // k-major, [k][j] stride 65
    __shared__ float sWrT[32 * 65];
    __shared__ __align__(16) float sM[32][32];
    __shared__ __align__(16) float sX[32][32];
    int tid  = threadIdx.x;
    int w    = tid >> 5;
    int lane = tid & 31;
    int nb32 = blockIdx.x * 32;

    for (int i = tid; i < 64 * 32; i += 256) {
        int j = i >> 5, k = i & 31;
        sWlT[k * 65 + j] = W_l[i];
        sWrT[k * 65 + j] = W_r[i];
    }

    #pragma unroll
    for (int u = 0; u < 4; u++) {
        int n = nb32 + w * 4 + u;
        int beg = __ldg(g_rowptr + n), end = __ldg(g_rowptr + n + 1);
        float acc = 0.f;
        for (int e = beg; e < end; e += 16) {
            #pragma unroll
            for (int i = 0; i < 16; i++) {
                int ok  = (e + i < end);
                int idx = ok ? e + i : beg;
                int s   = __ldg(g_srclist + idx);
                float a = __half2float(__ldg(g_x16 + (long long)s * 32 + lane));
                acc += ok ? a : 0.f;
            }
        }
        float inv = 1.f / fmaxf((float)(end - beg), 1.f);
        sM[w * 4 + u][lane] = acc * inv;
        sX[w * 4 + u][lane] = __ldg(x + (long long)n * 32 + lane);
    }
    __syncthreads();

    int grp = tid >> 6;         // 0..3
    int j   = tid & 63;
    int uB  = grp * 8;
    float bj = __ldg(b + j);

    float acc[8];
    #pragma unroll
    for (int u = 0; u < 8; u++) acc[u] = bj;

    #pragma unroll
    for (int k = 0; k < 32; k += 4) {
        float wl0 = sWlT[(k + 0) * 65 + j], wl1 = sWlT[(k + 1) * 65 + j];
        float wl2 = sWlT[(k + 2) * 65 + j], wl3 = sWlT[(k + 3) * 65 + j];
        float wr0 = sWrT[(k + 0) * 65 + j], wr1 = sWrT[(k + 1) * 65 + j];
        float wr2 = sWrT[(k + 2) * 65 + j], wr3 = sWrT[(k + 3) * 65 + j];
        #pragma unroll
        for (int u = 0; u < 8; u++) {
            float4 m = *(const float4*)&sM[uB + u][k];
            float4 v = *(const float4*)&sX[uB + u][k];
            acc[u] += m.x * wl0 + m.y * wl1 + m.z * wl2 + m.w * wl3
                    + v.x * wr0 + v.y * wr1 + v.z * wr2 + v.w * wr3;
        }
    }
    #pragma unroll
    for (int u = 0; u < 8; u++) {
        int n = nb32 + uB + u;
        g_h1[(long long)n * 64 + j] = __float2half(fmaxf(acc[u], 0.f));
    }
}

// ---------------------------------------------------------------------------
// Fused conv2 + pool: 8 warps each gather-mean 4 nodes (64-dim, half2 lanes),
// predicated 16-wide loop, then transform + run-length pooled atomics.
// ---------------------------------------------------------------------------
__global__ __launch_bounds__(256) void k_conv2pool(const float* __restrict__ W_l,
                                                   const float* __restrict__ b,
                                                   const float* __restrict__ W_r,
                                                   const int* __restrict__ batch) {
    __shared__ float sWlT[64 * 65];
    __shared__ float sWrT[64 * 65];
    __shared__ __align__(16) float sM[32][64];
    __shared__ __align__(16) float sH[32][64];
    int tid  = threadIdx.x;
    int w    = tid >> 5;
    int lane = tid & 31;
    int nb32 = blockIdx.x * 32;

    for (int i = tid; i < 64 * 64; i += 256) {
        int j = i >> 6, k = i & 63;
        sWlT[k * 65 + j] = W_l[i];
        sWrT[k * 65 + j] = W_r[i];
    }

    #pragma unroll
    for (int u = 0; u < 4; u++) {
        int n = nb32 + w * 4 + u;
        int beg = __ldg(g_rowptr + n), end = __ldg(g_rowptr + n + 1);
        float ax = 0.f, ay = 0.f;
        for (int e = beg; e < end; e += 16) {
            #pragma unroll
            for (int i = 0; i < 16; i++) {
                int ok  = (e + i < end);
                int idx = ok ? e + i : beg;
                int s   = __ldg(g_srclist + idx);
                float2 v = __half22float2(
                    __ldg((const __half2*)(g_h1 + (long long)s * 64) + lane));
                ax += ok ? v.x : 0.f;
                ay += ok ? v.y : 0.f;
            }
        }
        float inv = 1.f / fmaxf((float)(end - beg), 1.f);
        sM[w * 4 + u][lane * 2 + 0] = ax * inv;
        sM[w * 4 + u][lane * 2 + 1] = ay * inv;
        float2 hs = __half22float2(__ldg((const __half2*)(g_h1 + (long long)n * 64) + lane));
        sH[w * 4 + u][lane * 2 + 0] = hs.x;
        sH[w * 4 + u][lane * 2 + 1] = hs.y;
    }
    __syncthreads();

    int grp = tid >> 6;
    int j   = tid & 63;
    int uB  = grp * 8;
    float bj = __ldg(b + j);

    float acc[8];
    #pragma unroll
    for (int u = 0; u < 8; u++) acc[u] = bj;

    #pragma unroll
    for (int k = 0; k < 64; k += 4) {
        float wl0 = sWlT[(k + 0) * 65 + j], wl1 = sWlT[(k + 1) * 65 + j];
        float wl2 = sWlT[(k + 2) * 65 + j], wl3 = sWlT[(k + 3) * 65 + j];
        float wr0 = sWrT[(k + 0) * 65 + j], wr1 = sWrT[(k + 1) * 65 + j];
        float wr2 = sWrT[(k + 2) * 65 + j], wr3 = sWrT[(k + 3) * 65 + j];
        #pragma unroll
        for (int u = 0; u < 8; u++) {
            float4 m = *(const float4*)&sM[uB + u][k];
            float4 h = *(const float4*)&sH[uB + u][k];
            acc[u] += m.x * wl0 + m.y * wl1 + m.z * wl2 + m.w * wl3
                    + h.x * wr0 + h.y * wr1 + h.z * wr2 + h.w * wr3;
        }
    }

    // pool with run-length merge (batch is sorted)
    int nb = nb32 + uB;
    int gcur = __ldg(batch + nb);
    float run = 0.f;
    #pragma unroll
    for (int u = 0; u < 8; u++) {
        float v = fmaxf(acc[u], 0.f);
        int g = __ldg(batch + nb + u);
        if (g != gcur) {
            atomicAdd(&g_pool[(long long)gcur * 64 + j], run);
            run = v; gcur = g;
        } else {
            run += v;
        }
    }
    atomicAdd(&g_pool[(long long)gcur * 64 + j], run);
}

// ---------------------------------------------------------------------------
// Head: out[g] = (pool[g]/cnt[g]) @ W_lin.T + b_lin; cnt via binary search
// ---------------------------------------------------------------------------
__device__ __forceinline__ int lowerb(const int* __restrict__ a, int n, int v) {
    int lo = 0, hi = n;
    while (lo < hi) {
        int m = (lo + hi) >> 1;
        if (__ldg(a + m) < v) lo = m + 1; else hi = m;
    }
    return lo;
}

__global__ __launch_bounds__(256) void k_final(const float* __restrict__ W_lin,
                                               const float* __restrict__ b_lin,
                                               const int* __restrict__ batch,
                                               float* __restrict__ out) {
    int g = blockIdx.x * blockDim.x + threadIdx.x;
    if (g >= N_GRAPHS) return;
    int cnt = lowerb(batch, N_NODES, g + 1) - lowerb(batch, N_NODES, g);
    float inv = 1.0f / fmaxf((float)cnt, 1.0f);
    float a0 = 0.f, a1 = 0.f;
    #pragma unroll
    for (int j = 0; j < 64; j++) {
        float p = g_pool[g * 64 + j] * inv;
        a0 += p * __ldg(W_lin + j);
        a1 += p * __ldg(W_lin + 64 + j);
    }
    out[g * 2 + 0] = a0 + __ldg(b_lin + 0);
    out[g * 2 + 1] = a1 + __ldg(b_lin + 1);
}

// ---------------------------------------------------------------------------
extern "C" void kernel_launch(void* const* d_in, const int* in_sizes, int n_in,
                              void* d_out, int out_size) {
    const float* x     = (const float*)d_in[0];
    const int*   ei    = (const int*)d_in[1];
    const int*   batch = (const int*)d_in[2];
    const float* W1_l  = (const float*)d_in[3];
    const float* b1    = (const float*)d_in[4];
    const float* W1_r  = (const float*)d_in[5];
    const float* W2_l  = (const float*)d_in[6];
    const float* b2    = (const float*)d_in[7];
    const float* W2_r  = (const float*)d_in[8];
    const float* W_lin = (const float*)d_in[9];
    const float* b_lin = (const float*)d_in[10];
    float* out = (float*)d_out;

    k_prep<<<512, 256>>>(x);
    k_hist<<<(N_EDGES / 4 + 255) / 256, 256>>>(ei);
    k_scan1<<<SCAN_NBLK, 512>>>();
    k_scan2<<<1, 128>>>();
    k_scan3<<<(N_NODES + 255) / 256, 256>>>();
    k_fill<<<(N_EDGES + 255) / 256, 256>>>(ei);
    k_conv1<<<N_NODES / 32, 256>>>(x, W1_l, b1, W1_r);
    k_conv2pool<<<N_NODES / 32, 256>>>(W2_l, b2, W2_r, batch);
    k_final<<<(N_GRAPHS + 255) / 256, 256>>>(W_lin, b_lin, batch, out);
}

// round 17
// speedup vs baseline: 1.0726x; 1.0726x over previous
#include <cuda_runtime.h>
#include <cuda_fp16.h>

#define N_NODES    200000
#define N_EDGES    3200000
#define N_GRAPHS   4000
#define SCAN_ELEMS 2048
#define SCAN_NBLK  ((N_NODES + SCAN_ELEMS - 1) / SCAN_ELEMS)   // 98

// ---------------- device scratch (no runtime allocation) --------------------
__device__ int    g_count[N_NODES];
__device__ int    g_rowptr[N_NODES + 1];
__device__ int    g_bsums[SCAN_NBLK];
__device__ int    g_rank[N_EDGES];
__device__ int    g_srclist[N_EDGES];
__device__ __half g_x16[N_NODES * 32];    // fp16 copy of x (for gathers)
__device__ __half g_h1[N_NODES * 64];     // relu(conv1), fp16
__device__ float  g_pool[N_GRAPHS * 64];

// ---------------------------------------------------------------------------
// Prep: zero counters/pool and convert x -> fp16
// ---------------------------------------------------------------------------
__global__ __launch_bounds__(256) void k_prep(const float* __restrict__ x) {
    int i = blockIdx.x * blockDim.x + threadIdx.x;
    int stride = gridDim.x * blockDim.x;
    for (int t = i; t < N_NODES * 16; t += stride) {       // 3.2M half2
        float2 v = __ldg((const float2*)x + t);
        ((__half2*)g_x16)[t] = __floats2half2_rn(v.x, v.y);
    }
    for (int t = i; t < N_NODES; t += stride) g_count[t] = 0;
    for (int t = i; t < N_GRAPHS * 64; t += stride) g_pool[t] = 0.f;
}

// ---------------------------------------------------------------------------
// CSR build: histogram of dst; atomic return value IS the within-bucket rank.
// ---------------------------------------------------------------------------
__global__ __launch_bounds__(256) void k_hist(const int* __restrict__ ei) {
    int t = blockIdx.x * blockDim.x + threadIdx.x;
    int e = t * 4;
    if (e >= N_EDGES) return;
    int4 d4 = __ldg((const int4*)(ei + N_EDGES) + t);
    g_rank[e + 0] = atomicAdd(&g_count[d4.x], 1);
    g_rank[e + 1] = atomicAdd(&g_count[d4.y], 1);
    g_rank[e + 2] = atomicAdd(&g_count[d4.z], 1);
    g_rank[e + 3] = atomicAdd(&g_count[d4.w], 1);
}

// Scan pass 1: per-block exclusive scan of counts (2048 elems / block of 512)
__global__ __launch_bounds__(512) void k_scan1() {
    __shared__ int warp_sums[16];
    int t = threadIdx.x;
    int base = blockIdx.x * SCAN_ELEMS + t * 4;
    int c0 = (base + 0 < N_NODES) ? g_count[base + 0] : 0;
    int c1 = (base + 1 < N_NODES) ? g_count[base + 1] : 0;
    int c2 = (base + 2 < N_NODES) ? g_count[base + 2] : 0;
    int c3 = (base + 3 < N_NODES) ? g_count[base + 3] : 0;
    int s = c0 + c1 + c2 + c3;
    int lane = t & 31, wid = t >> 5;
    int v = s;
    #pragma unroll
    for (int o = 1; o < 32; o <<= 1) {
        int u = __shfl_up_sync(0xFFFFFFFFu, v, o);
        if (lane >= o) v += u;
    }
    if (lane == 31) warp_sums[wid] = v;
    __syncthreads();
    if (wid == 0) {
        int w = (lane < 16) ? warp_sums[lane] : 0;
        #pragma unroll
        for (int o = 1; o < 16; o <<= 1) {
            int u = __shfl_up_sync(0xFFFFFFFFu, w, o);
            if (lane >= o) w += u;
        }
        if (lane < 16) warp_sums[lane] = w;
    }
    __syncthreads();
    int excl = v - s + (wid > 0 ? warp_sums[wid - 1] : 0);
    if (base + 0 < N_NODES) g_rowptr[base + 0] = excl;
    if (base + 1 < N_NODES) g_rowptr[base + 1] = excl + c0;
    if (base + 2 < N_NODES) g_rowptr[base + 2] = excl + c0 + c1;
    if (base + 3 < N_NODES) g_rowptr[base + 3] = excl + c0 + c1 + c2;
    if (t == 511) g_bsums[blockIdx.x] = warp_sums[15];
}

// Scan pass 2: exclusive scan of 98 block sums (single block)
__global__ __launch_bounds__(128) void k_scan2() {
    __shared__ int sh[128];
    int t = threadIdx.x;
    sh[t] = (t < SCAN_NBLK) ? g_bsums[t] : 0;
    __syncthreads();
    int v = sh[t];
    #pragma unroll
    for (int o = 1; o < 128; o <<= 1) {
        int u = (t >= o) ? sh[t - o] : 0;
        __syncthreads();
        v += u;
        sh[t] = v;
        __syncthreads();
    }
    if (t < SCAN_NBLK) g_bsums[t] = (t > 0) ? sh[t - 1] : 0;
}

// Scan pass 3: add block offsets
__global__ __launch_bounds__(256) void k_scan3() {
    int i = blockIdx.x * blockDim.x + threadIdx.x;
    if (i == 0) g_rowptr[N_NODES] = N_EDGES;
    if (i >= N_NODES) return;
    g_rowptr[i] += g_bsums[i / SCAN_ELEMS];
}

// CSR fill, atomic-free: pos = rowptr[dst] + rank[e]
__global__ __launch_bounds__(256) void k_fill(const int* __restrict__ ei) {
    int e = blockIdx.x * blockDim.x + threadIdx.x;
    if (e >= N_EDGES) return;
    int s = __ldg(ei + e);
    int d = __ldg(ei + N_EDGES + e);
    int pos = __ldg(g_rowptr + d) + __ldg(g_rank + e);
    g_srclist[pos] = s;
}

// ---------------------------------------------------------------------------
// Fused conv1: 8 warps each gather-mean 4 nodes from fp16 x using the
// PAIR-GATHER trick: one LDG loads TWO 64B rows (lanes 0-15 row A, 16-31
// row B, half2 per lane); shfl_xor(16) merges halves. Then register-blocked
// transform: h1 = relu(mean @ W1_l.T + b1 + x @ W1_r.T), h1 stored fp16.
// ---------------------------------------------------------------------------
__global__ __launch_bounds__(256) void k_conv1(const float* __restrict__ x,
                                               const float* __restrict__ W_l,
                                               const float* __restrict__ b,
                                               const float* __restrict__ W_r) {
    __shared__ float sWlT[32 * 65];   // k-major, [k][j] stride 65
    __shared__ float sWrT[32 * 65];
    __shared__ __align__(16) float sM[32][32];
    __shared__ __align__(16) float sX[32][32];
    int tid  = threadIdx.x;
    int w    = tid >> 5;
    int lane = tid & 31;
    int half = lane >> 4;       // 0: even edges, 1: odd edges
    int hl   = lane & 15;       // half2 index within row (covers dims 2hl, 2hl+1)
    int nb32 = blockIdx.x * 32;

    for (int i = tid; i < 64 * 32; i += 256) {
        int j = i >> 5, k = i & 31;
        sWlT[k * 65 + j] = W_l[i];
        sWrT[k * 65 + j] = W_r[i];
    }

    #pragma unroll
    for (int u = 0; u < 4; u++) {
        int n = nb32 + w * 4 + u;
        int beg = __ldg(g_rowptr + n), end = __ldg(g_rowptr + n + 1);
        float ax = 0.f, ay = 0.f;
        int e = beg;
        for (; e + 8 <= end; e += 8) {          // 4 pair-LDGs = 8 rows in flight
            #pragma unroll
            for (int i = 0; i < 4; i++) {
                int s = __ldg(g_srclist + e + 2 * i + half);
                float2 f = __half22float2(
                    __ldg((const __half2*)g_x16 + (long long)s * 16 + hl));
                ax += f.x; ay += f.y;
            }
        }
        for (; e + 2 <= end; e += 2) {          // pair tail
            int s = __ldg(g_srclist + e + half);
            float2 f = __half22float2(
                __ldg((const __half2*)g_x16 + (long long)s * 16 + hl));
            ax += f.x; ay += f.y;
        }
        if (e < end) {                           // odd single edge
            int s = __ldg(g_srclist + e);
            if (half == 0) {
                float2 f = __half22float2(
                    __ldg((const __half2*)g_x16 + (long long)s * 16 + hl));
                ax += f.x; ay += f.y;
            }
        }
        ax += __shfl_xor_sync(0xFFFFFFFFu, ax, 16);
        ay += __shfl_xor_sync(0xFFFFFFFFu, ay, 16);
        float inv = 1.f / fmaxf((float)(end - beg), 1.f);
        if (half == 0) {
            sM[w * 4 + u][hl * 2 + 0] = ax * inv;
            sM[w * 4 + u][hl * 2 + 1] = ay * inv;
        }
        sX[w * 4 + u][lane] = __ldg(x + (long long)n * 32 + lane);
    }
    __syncthreads();

    int grp = tid >> 6;         // 0..3
    int j   = tid & 63;
    int uB  = grp * 8;
    float bj = __ldg(b + j);

    float acc[8];
    #pragma unroll
    for (int u = 0; u < 8; u++) acc[u] = bj;

    #pragma unroll
    for (int k = 0; k < 32; k += 4) {
        float wl0 = sWlT[(k + 0) * 65 + j], wl1 = sWlT[(k + 1) * 65 + j];
        float wl2 = sWlT[(k + 2) * 65 + j], wl3 = sWlT[(k + 3) * 65 + j];
        float wr0 = sWrT[(k + 0) * 65 + j], wr1 = sWrT[(k + 1) * 65 + j];
        float wr2 = sWrT[(k + 2) * 65 + j], wr3 = sWrT[(k + 3) * 65 + j];
        #pragma unroll
        for (int u = 0; u < 8; u++) {
            float4 m = *(const float4*)&sM[uB + u][k];
            float4 v = *(const float4*)&sX[uB + u][k];
            acc[u] += m.x * wl0 + m.y * wl1 + m.z * wl2 + m.w * wl3
                    + v.x * wr0 + v.y * wr1 + v.z * wr2 + v.w * wr3;
        }
    }
    #pragma unroll
    for (int u = 0; u < 8; u++) {
        int n = nb32 + uB + u;
        g_h1[(long long)n * 64 + j] = __float2half(fmaxf(acc[u], 0.f));
    }
}

// ---------------------------------------------------------------------------
// Fused conv2 + pool: 8 warps each gather-mean 4 nodes (64-dim fp16 rows,
// half2 per lane, 8 rows in flight), then transform + run-length pool.
// ---------------------------------------------------------------------------
__global__ __launch_bounds__(256) void k_conv2pool(const float* __restrict__ W_l,
                                                   const float* __restrict__ b,
                                                   const float* __restrict__ W_r,
                                                   const int* __restrict__ batch) {
    __shared__ float sWlT[64 * 65];
    __shared__ float sWrT[64 * 65];
    __shared__ __align__(16) float sM[32][64];
    __shared__ __align__(16) float sH[32][64];
    int tid  = threadIdx.x;
    int w    = tid >> 5;
    int lane = tid & 31;
    int nb32 = blockIdx.x * 32;

    for (int i = tid; i < 64 * 64; i += 256) {
        int j = i >> 6, k = i & 63;
        sWlT[k * 65 + j] = W_l[i];
        sWrT[k * 65 + j] = W_r[i];
    }

    #pragma unroll
    for (int u = 0; u < 4; u++) {
        int n = nb32 + w * 4 + u;
        int beg = __ldg(g_rowptr + n), end = __ldg(g_rowptr + n + 1);
        float ax = 0.f, ay = 0.f;
        int e = beg;
        for (; e + 8 <= end; e += 8) {
            int s0 = __ldg(g_srclist + e + 0);
            int s1 = __ldg(g_srclist + e + 1);
            int s2 = __ldg(g_srclist + e + 2);
            int s3 = __ldg(g_srclist + e + 3);
            int s4 = __ldg(g_srclist + e + 4);
            int s5 = __ldg(g_srclist + e + 5);
            int s6 = __ldg(g_srclist + e + 6);
            int s7 = __ldg(g_srclist + e + 7);
            float2 v0 = __half22float2(__ldg((const __half2*)(g_h1 + (long long)s0 * 64) + lane));
            float2 v1 = __half22float2(__ldg((const __half2*)(g_h1 + (long long)s1 * 64) + lane));
            float2 v2 = __half22float2(__ldg((const __half2*)(g_h1 + (long long)s2 * 64) + lane));
            float2 v3 = __half22float2(__ldg((const __half2*)(g_h1 + (long long)s3 * 64) + lane));
            float2 v4 = __half22float2(__ldg((const __half2*)(g_h1 + (long long)s4 * 64) + lane));
            float2 v5 = __half22float2(__ldg((const __half2*)(g_h1 + (long long)s5 * 64) + lane));
            float2 v6 = __half22float2(__ldg((const __half2*)(g_h1 + (long long)s6 * 64) + lane));
            float2 v7 = __half22float2(__ldg((const __half2*)(g_h1 + (long long)s7 * 64) + lane));
            ax += ((v0.x + v1.x) + (v2.x + v3.x)) + ((v4.x + v5.x) + (v6.x + v7.x));
            ay += ((v0.y + v1.y) + (v2.y + v3.y)) + ((v4.y + v5.y) + (v6.y + v7.y));
        }
        for (; e < end; ++e) {
            float2 v = __half22float2(
                __ldg((const __half2*)(g_h1 + (long long)__ldg(g_srclist + e) * 64) + lane));
            ax += v.x; ay += v.y;
        }
        float inv = 1.f / fmaxf((float)(end - beg), 1.f);
        sM[w * 4 + u][lane * 2 + 0] = ax * inv;
        sM[w * 4 + u][lane * 2 + 1] = ay * inv;
        float2 hs = __half22float2(__ldg((const __half2*)(g_h1 + (long long)n * 64) + lane));
        sH[w * 4 + u][lane * 2 + 0] = hs.x;
        sH[w * 4 + u][lane * 2 + 1] = hs.y;
    }
    __syncthreads();

    int grp = tid >> 6;
    int j   = tid & 63;
    int uB  = grp * 8;
    float bj = __ldg(b + j);

    float acc[8];
    #pragma unroll
    for (int u = 0; u < 8; u++) acc[u] = bj;

    #pragma unroll
    for (int k = 0; k < 64; k += 4) {
        float wl0 = sWlT[(k + 0) * 65 + j], wl1 = sWlT[(k + 1) * 65 + j];
        float wl2 = sWlT[(k + 2) * 65 + j], wl3 = sWlT[(k + 3) * 65 + j];
        float wr0 = sWrT[(k + 0) * 65 + j], wr1 = sWrT[(k + 1) * 65 + j];
        float wr2 = sWrT[(k + 2) * 65 + j], wr3 = sWrT[(k + 3) * 65 + j];
        #pragma unroll
        for (int u = 0; u < 8; u++) {
            float4 m = *(const float4*)&sM[uB + u][k];
            float4 h = *(const float4*)&sH[uB + u][k];
            acc[u] += m.x * wl0 + m.y * wl1 + m.z * wl2 + m.w * wl3
                    + h.x * wr0 + h.y * wr1 + h.z * wr2 + h.w * wr3;
        }
    }

    // pool with run-length merge (batch is sorted)
    int nb = nb32 + uB;
    int gcur = __ldg(batch + nb);
    float run = 0.f;
    #pragma unroll
    for (int u = 0; u < 8; u++) {
        float v = fmaxf(acc[u], 0.f);
        int g = __ldg(batch + nb + u);
        if (g != gcur) {
            atomicAdd(&g_pool[(long long)gcur * 64 + j], run);
            run = v; gcur = g;
        } else {
            run += v;
        }
    }
    atomicAdd(&g_pool[(long long)gcur * 64 + j], run);
}

// ---------------------------------------------------------------------------
// Head: out[g] = (pool[g]/cnt[g]) @ W_lin.T + b_lin; cnt via binary search
// ---------------------------------------------------------------------------
__device__ __forceinline__ int lowerb(const int* __restrict__ a, int n, int v) {
    int lo = 0, hi = n;
    while (lo < hi) {
        int m = (lo + hi) >> 1;
        if (__ldg(a + m) < v) lo = m + 1; else hi = m;
    }
    return lo;
}

__global__ __launch_bounds__(256) void k_final(const float* __restrict__ W_lin,
                                               const float* __restrict__ b_lin,
                                               const int* __restrict__ batch,
                                               float* __restrict__ out) {
    int g = blockIdx.x * blockDim.x + threadIdx.x;
    if (g >= N_GRAPHS) return;
    int cnt = lowerb(batch, N_NODES, g + 1) - lowerb(batch, N_NODES, g);
    float inv = 1.0f / fmaxf((float)cnt, 1.0f);
    float a0 = 0.f, a1 = 0.f;
    #pragma unroll
    for (int j = 0; j < 64; j++) {
        float p = g_pool[g * 64 + j] * inv;
        a0 += p * __ldg(W_lin + j);
        a1 += p * __ldg(W_lin + 64 + j);
    }
    out[g * 2 + 0] = a0 + __ldg(b_lin + 0);
    out[g * 2 + 1] = a1 + __ldg(b_lin + 1);
}

// ---------------------------------------------------------------------------
extern "C" void kernel_launch(void* const* d_in, const int* in_sizes, int n_in,
                              void* d_out, int out_size) {
    const float* x     = (const float*)d_in[0];
    const int*   ei    = (const int*)d_in[1];
    const int*   batch = (const int*)d_in[2];
    const float* W1_l  = (const float*)d_in[3];
    const float* b1    = (const float*)d_in[4];
    const float* W1_r  = (const float*)d_in[5];
    const float* W2_l  = (const float*)d_in[6];
    const float* b2    = (const float*)d_in[7];
    const float* W2_r  = (const float*)d_in[8];
    const float* W_lin = (const float*)d_in[9];
    const float* b_lin = (const float*)d_in[10];
    float* out = (float*)d_out;

    k_prep<<<512, 256>>>(x);
    k_hist<<<(N_EDGES / 4 + 255) / 256, 256>>>(ei);
    k_scan1<<<SCAN_NBLK, 512>>>();
    k_scan2<<<1, 128>>>();
    k_scan3<<<(N_NODES + 255) / 256, 256>>>();
    k_fill<<<(N_EDGES + 255) / 256, 256>>>(ei);
    k_conv1<<<N_NODES / 32, 256>>>(x, W1_l, b1, W1_r);
    k_conv2pool<<<N_NODES / 32, 256>>>(W2_l, b2, W2_r, batch);
    k_final<<<(N_GRAPHS + 255) / 256, 256>>>(W_lin, b_lin, batch, out);
}